// round 6
// baseline (speedup 1.0000x reference)
#include <cuda_runtime.h>

#define M_   64
#define L_   32
#define P_   100
#define NC_  400
#define NQUAD_ (NC_/4)                     // 100 C-quads
#define PTS_PER_BLK 5
#define ITEMS_PER_PT (NQUAD_ + 1)          // 100 quads + 1 e00
#define TWO_PI_F 6.28318530717958647692f

typedef unsigned long long ull;

struct Layer { float d, inv_a, inv_b, b2, rho, inv_rho; };

__device__ Layer g_layers[M_ * L_];
__device__ float g_rng[M_ * P_];
__device__ float g_e00[M_ * P_];

// ---------------------------------------------------------------------------
// Packed fp32x2 helpers
// ---------------------------------------------------------------------------
struct F2 { ull v; };
__device__ __forceinline__ F2 f2pk(float a, float b) {
    F2 r; asm("mov.b64 %0,{%1,%2};" : "=l"(r.v) : "f"(a), "f"(b)); return r;
}
__device__ __forceinline__ void f2up(F2 a, float& x, float& y) {
    asm("mov.b64 {%0,%1},%2;" : "=f"(x), "=f"(y) : "l"(a.v));
}
__device__ __forceinline__ F2 f2mul(F2 a, F2 b) {
    F2 r; asm("mul.rn.f32x2 %0,%1,%2;" : "=l"(r.v) : "l"(a.v), "l"(b.v)); return r;
}
__device__ __forceinline__ F2 f2add(F2 a, F2 b) {
    F2 r; asm("add.rn.f32x2 %0,%1,%2;" : "=l"(r.v) : "l"(a.v), "l"(b.v)); return r;
}
__device__ __forceinline__ F2 f2sub(F2 a, F2 b) {
    F2 r; asm("sub.rn.f32x2 %0,%1,%2;" : "=l"(r.v) : "l"(a.v), "l"(b.v)); return r;
}
__device__ __forceinline__ F2 f2fma(F2 a, F2 b, F2 c) {
    F2 r; asm("fma.rn.f32x2 %0,%1,%2,%3;" : "=l"(r.v) : "l"(a.v), "l"(b.v), "l"(c.v)); return r;
}
__device__ __forceinline__ float frsqa(float x) {
    float r; asm("rsqrt.approx.f32 %0,%1;" : "=f"(r) : "f"(x)); return r;
}
__device__ __forceinline__ float fsqrta(float x) {
    float r; asm("sqrt.approx.f32 %0,%1;" : "=f"(r) : "f"(x)); return r;
}
__device__ __forceinline__ ull dupf(float f) {
    unsigned u = __float_as_uint(f); return ((ull)u << 32) | (ull)u;
}
__device__ __forceinline__ unsigned ford(float f) {
    unsigned u = __float_as_uint(f);
    return (u & 0x80000000u) ? ~u : (u | 0x80000000u);
}
__device__ __forceinline__ float funord(unsigned u) {
    return (u & 0x80000000u) ? __uint_as_float(u & 0x7FFFFFFFu) : __uint_as_float(~u);
}

// ---------------------------------------------------------------------------
// Branchless _var for one lane; 2 exp (fac = ep^2, a0 = sel(ep)*sel(eq)).
// Range facts (t>=0.5, C>=1, v>=1.2, d<=1): p,q<16 and exa<60 cutoffs dead.
// ---------------------------------------------------------------------------
__device__ __forceinline__ void var_lane(
    float wv, float wv2, float dm, float xka, float xka2, float xkb, float xkb2,
    float& cosp, float& cosq, float& w, float& x, float& y, float& z, float& a0)
{
    float ra2 = fabsf(wv2 - xka2), rb2 = fabsf(wv2 - xkb2);
    float ira = frsqa(ra2), irb = frsqa(rb2);
    float ra = (ra2 > 0.0f) ? ra2 * ira : 0.0f;
    float rb = (rb2 > 0.0f) ? rb2 * irb : 0.0f;
    float p = ra * dm, q = rb * dm;
    float sinp, cosp_o; __sincosf(p, &sinp, &cosp_o);
    float sinq, cosq_o; __sincosf(q, &sinq, &cosq_o);
    float ep = __expf(-p), eq = __expf(-q);
    float fp = ep * ep, fq = eq * eq;
    float cpe = fmaf(0.5f, fp, 0.5f), spe = fmaf(-0.5f, fp, 0.5f);
    float cqe = fmaf(0.5f, fq, 0.5f), sqe = fmaf(-0.5f, fq, 0.5f);
    bool lt_a = wv < xka, gt_a = wv > xka;
    bool lt_b = wv < xkb, gt_b = wv > xkb;
    cosp = lt_a ? cosp_o : cpe;
    cosq = lt_b ? cosq_o : cqe;
    w = lt_a ? sinp * ira : (gt_a ? spe * ira : dm);
    x = lt_a ? -ra * sinp : ra * spe;
    y = lt_b ? sinq * irb : (gt_b ? sqe * irb : dm);
    z = lt_b ? -rb * sinq : rb * sqe;
    a0 = (lt_a ? 1.0f : ep) * (lt_b ? 1.0f : eq);
}

__device__ __forceinline__ void half_lane(
    float wv2, float xka2h, float xkb2h, float gmkh, float rhoh,
    float& e0, float& e1, float& e2, float& e3, float& e4)
{
    float ra = fsqrta(fabsf(wv2 - xka2h));
    float rb = fsqrta(fabsf(wv2 - xkb2h));
    float gam = gmkh * wv2, gamm1 = gam - 1.0f;
    float rarb = ra * rb;
    e0 = rhoh * rhoh * (gamm1 * gamm1 - gam * gmkh * rarb);
    e1 = -rhoh * ra;
    e2 = rhoh * (gamm1 - gmkh * rarb);
    e3 = rhoh * rb;
    e4 = wv2 - rarb;
}

// ---------------------------------------------------------------------------
__global__ void prepKernel(const float* __restrict__ d, const float* __restrict__ b) {
    int i = blockIdx.x * blockDim.x + threadIdx.x;
    if (i >= M_ * L_) return;
    float bb = b[i];
    float b2 = bb * bb, b3 = b2 * bb, b4 = b2 * b2;
    float a = 0.9409f + 2.0947f * bb - 0.8206f * b2 + 0.2683f * b3 - 0.0251f * b4;
    float a2 = a * a, a3 = a2 * a, a4 = a2 * a2, a5 = a4 * a;
    float rho = 1.6612f * a - 0.4721f * a2 + 0.0671f * a3 - 0.0043f * a4 + 0.000106f * a5;
    Layer ly;
    ly.d = d[i]; ly.inv_a = 1.0f / a; ly.inv_b = 1.0f / bb;
    ly.b2 = b2;  ly.rho = rho;        ly.inv_rho = 1.0f / rho;
    g_layers[i] = ly;
}

__global__ void dummyKernel() {}   // ncu capture alignment

// ---------------------------------------------------------------------------
// Det grid: 5 points/block; each thread runs a QUAD of C values = two packed
// pairs (independent E chains -> 2x ILP). Both pairs share the point, so layer
// constants are loaded once per step for both chains.
// ---------------------------------------------------------------------------
__global__ void __launch_bounds__(128, 5) detKernel(const float* __restrict__ tlist,
                                                    const float* __restrict__ Clist,
                                                    const float* __restrict__ vlist) {
    __shared__ float sD[PTS_PER_BLK * L_], sXka[PTS_PER_BLK * L_], sXka2[PTS_PER_BLK * L_];
    __shared__ float sXkb[PTS_PER_BLK * L_], sXkb2[PTS_PER_BLK * L_];
    __shared__ ull pGmk[PTS_PER_BLK * L_], pRho[PTS_PER_BLK * L_], pNRho[PTS_PER_BLK * L_],
                   pNRho2[PTS_PER_BLK * L_], pRhoI[PTS_PER_BLK * L_], pNRhoI[PTS_PER_BLK * L_],
                   pNRhoI2[PTS_PER_BLK * L_];
    __shared__ float sGmkH[PTS_PER_BLK], sRhoH[PTS_PER_BLK];
    __shared__ float sOmg[PTS_PER_BLK], sV[PTS_PER_BLK];
    __shared__ unsigned sMnU[PTS_PER_BLK], sMxU[PTS_PER_BLK];
    __shared__ float shC[NC_];

    int tid = threadIdx.x;
    int p0 = blockIdx.x * PTS_PER_BLK;
    int npts = min(PTS_PER_BLK, M_ * P_ - p0);

    if (tid < npts) {
        sOmg[tid] = TWO_PI_F / tlist[p0 + tid];
        sV[tid] = vlist[p0 + tid];
        sMnU[tid] = 0xFFFFFFFFu;
        sMxU[tid] = 0u;
    }
    for (int i = tid; i < npts * L_; i += 128) {
        int s = i >> 5, l = i & 31;
        int pt = p0 + s;
        float omega = fmaxf(TWO_PI_F / tlist[pt], 1e-4f);
        Layer ly = g_layers[(pt / P_) * L_ + l];
        float xka = omega * ly.inv_a, xkb = omega * ly.inv_b;
        float iw = __fdividef(1.0f, omega);
        float gmk = 2.0f * ly.b2 * iw * iw;
        sD[i] = ly.d; sXka[i] = xka; sXka2[i] = xka * xka;
        sXkb[i] = xkb; sXkb2[i] = xkb * xkb;
        pGmk[i]    = dupf(gmk);
        pRho[i]    = dupf(ly.rho);
        pNRho[i]   = dupf(-ly.rho);
        pNRho2[i]  = dupf(-ly.rho * ly.rho);
        pRhoI[i]   = dupf(ly.inv_rho);
        pNRhoI[i]  = dupf(-ly.inv_rho);
        pNRhoI2[i] = dupf(-ly.inv_rho * ly.inv_rho);
        if (l == L_ - 1) { sGmkH[s] = gmk; sRhoH[s] = ly.rho; }
    }
    for (int i = tid; i < NC_; i += 128) shC[i] = Clist[i];
    __syncthreads();

    int nit = npts * ITEMS_PER_PT;
    #pragma unroll 1
    for (int base = 0; base < nit; base += 128) {
        int it = base + tid;
        bool valid = it < nit;
        int itc = valid ? it : nit - 1;
        int j = itc / ITEMS_PER_PT;
        int local = itc - j * ITEMS_PER_PT;
        int jo = j << 5;
        bool is_e00 = (local == NQUAD_);
        float omega_raw = sOmg[j];
        float vv = sV[j];
        int cb = 4 * local;
        float den0 = is_e00 ? vv : shC[cb];
        float den1 = is_e00 ? vv : shC[cb + 1];
        float den2 = is_e00 ? vv : shC[cb + 2];
        float den3 = is_e00 ? vv : shC[cb + 3];
        float wv0 = __fdividef(omega_raw, den0);
        float wv1 = __fdividef(omega_raw, den1);
        float wv2_ = __fdividef(omega_raw, den2);
        float wv3 = __fdividef(omega_raw, den3);
        float w20 = wv0 * wv0, w21 = wv1 * wv1, w22 = wv2_ * wv2_, w23 = wv3 * wv3;
        F2 W2A = f2pk(w20, w21), W2B = f2pk(w22, w23);
        F2 TpA = f2pk(-2.0f * w20, -2.0f * w21), TpB = f2pk(-2.0f * w22, -2.0f * w23);
        F2 ONE = f2pk(1.0f, 1.0f);

        float xka2_h = sXka2[jo + L_ - 1], xkb2_h = sXkb2[jo + L_ - 1];
        float gmk_h = sGmkH[j], rho_h = sRhoH[j];
        F2 EA0, EA1, EA2, EA3, EA4, EB0, EB1, EB2, EB3, EB4;
        {
            float a0_, a1_, a2_, a3_, a4_, b0_, b1_, b2_, b3_, b4_;
            half_lane(w20, xka2_h, xkb2_h, gmk_h, rho_h, a0_, a1_, a2_, a3_, a4_);
            half_lane(w21, xka2_h, xkb2_h, gmk_h, rho_h, b0_, b1_, b2_, b3_, b4_);
            EA0 = f2pk(a0_, b0_); EA1 = f2pk(a1_, b1_); EA2 = f2pk(a2_, b2_);
            EA3 = f2pk(a3_, b3_); EA4 = f2pk(a4_, b4_);
            half_lane(w22, xka2_h, xkb2_h, gmk_h, rho_h, a0_, a1_, a2_, a3_, a4_);
            half_lane(w23, xka2_h, xkb2_h, gmk_h, rho_h, b0_, b1_, b2_, b3_, b4_);
            EB0 = f2pk(a0_, b0_); EB1 = f2pk(a1_, b1_); EB2 = f2pk(a2_, b2_);
            EB3 = f2pk(a3_, b3_); EB4 = f2pk(a4_, b4_);
        }

        // dnka + matvec for one packed pair (shared layer constants captured)
        F2 Gmk, Rho, NRho, NRho2, RhoI, NRhoI, NRhoI2;
        auto dnka = [&](F2 W2, F2 Tp, F2 Cp, F2 Cq, F2 W, F2 X, F2 Y, F2 Z, F2 A0,
                        F2& E0, F2& E1, F2& E2, F2& E3, F2& E4) {
            F2 Gam  = f2mul(Gmk, W2);
            F2 cpcq = f2mul(Cp, Cq);
            F2 cpy = f2mul(Cp, Y), cpz = f2mul(Cp, Z);
            F2 cqw = f2mul(Cq, W), cqx = f2mul(Cq, X);
            F2 xy = f2mul(X, Y), xz = f2mul(X, Z), wy = f2mul(W, Y), wz = f2mul(W, Z);
            F2 gamm1 = f2sub(Gam, ONE);
            F2 twgm1 = f2add(Gam, gamm1);
            F2 gmgmk = f2mul(Gam, Gmk);
            F2 gmgm1 = f2mul(Gam, gamm1);
            F2 gm1sq = f2mul(gamm1, gamm1);
            F2 a0pq  = f2sub(A0, cpcq);
            F2 A2    = f2add(a0pq, a0pq);
            F2 w2wy  = f2mul(W2, wy);

            F2 u = f2fma(gm1sq, w2wy, f2mul(gmgmk, xz));
            u = f2fma(gmgm1, A2, u);
            F2 c00 = f2sub(cpcq, u);
            F2 c01 = f2mul(f2sub(f2mul(W2, cpy), cqx), RhoI);
            F2 v = f2fma(Gmk, xz, f2mul(gamm1, w2wy));
            v = f2fma(twgm1, a0pq, v);
            F2 c02 = f2mul(v, NRhoI);
            F2 c03 = f2mul(f2sub(cpz, f2mul(W2, cqw)), RhoI);
            F2 s = f2fma(W2, A2, xz);
            s = f2fma(W2, w2wy, s);
            F2 c04 = f2mul(s, NRhoI2);
            F2 c10 = f2mul(f2sub(f2mul(gmgmk, cpz), f2mul(gm1sq, cqw)), Rho);
            F2 c12 = f2sub(f2mul(Gmk, cpz), f2mul(gamm1, cqw));
            F2 c30 = f2mul(f2sub(f2mul(gm1sq, cpy), f2mul(gmgmk, cqx)), Rho);
            F2 c32 = f2sub(f2mul(gamm1, cpy), f2mul(Gmk, cqx));
            F2 gg   = f2mul(gmgmk, gm1sq);
            F2 gmk2 = f2mul(gmgmk, gmgmk);
            F2 g1q  = f2mul(gm1sq, gm1sq);
            F2 hh = f2fma(gmk2, xz, f2mul(g1q, wy));
            hh = f2fma(gg, A2, hh);
            F2 c40 = f2mul(hh, NRho2);
            F2 k1 = f2mul(f2mul(Gmk, gamm1), twgm1);
            F2 k2 = f2mul(gmgmk, Gmk);
            F2 k3 = f2mul(gamm1, gm1sq);
            F2 v2 = f2fma(k2, xz, f2mul(k3, wy));
            v2 = f2fma(k1, a0pq, v2);
            F2 c42 = f2mul(v2, NRho);
            F2 c20 = f2mul(Tp, c42), c21 = f2mul(Tp, c32);
            F2 c23 = f2mul(Tp, c12), c24 = f2mul(Tp, c02);
            F2 dd = f2sub(cpcq, c00);
            F2 c22 = f2add(A0, f2add(dd, dd));

            F2 ee0 = f2fma(E0, c00, f2fma(E1, c10, f2fma(E2, c20, f2fma(E3, c30, f2mul(E4, c40)))));
            F2 ee1 = f2fma(E0, c01, f2fma(E1, cpcq, f2fma(E2, c21, f2sub(f2mul(E4, c30), f2mul(E3, xy)))));
            F2 ee2 = f2fma(E0, c02, f2fma(E1, c12, f2fma(E2, c22, f2fma(E3, c32, f2mul(E4, c42)))));
            F2 ee3 = f2fma(E0, c03, f2fma(E2, c23, f2fma(E3, cpcq, f2sub(f2mul(E4, c10), f2mul(E1, wz)))));
            F2 ee4 = f2fma(E0, c04, f2fma(E1, c03, f2fma(E2, c24, f2fma(E3, c01, f2mul(E4, c00)))));
            E0 = ee0; E1 = ee1; E2 = ee2; E3 = ee3; E4 = ee4;
        };

        auto normpair = [&](F2& E0, F2& E1, F2& E2, F2& E3, F2& E4) {
            float g0, q0, g1, q1, g2, q2, g3, q3, g4, q4;
            f2up(E0, g0, q0); f2up(E1, g1, q1); f2up(E2, g2, q2);
            f2up(E3, g3, q3); f2up(E4, g4, q4);
            float t1a = fmaxf(fmaxf(fabsf(g0), fabsf(g1)),
                              fmaxf(fmaxf(fabsf(g2), fabsf(g3)), fabsf(g4)));
            float t1b = fmaxf(fmaxf(fabsf(q0), fabsf(q1)),
                              fmaxf(fmaxf(fabsf(q2), fabsf(q3)), fabsf(q4)));
            t1a = fmaxf(t1a, 1e-30f);
            t1b = fmaxf(t1b, 1e-30f);
            F2 Ti = f2pk(__fdividef(1.0f, t1a), __fdividef(1.0f, t1b));
            E0 = f2mul(E0, Ti); E1 = f2mul(E1, Ti); E2 = f2mul(E2, Ti);
            E3 = f2mul(E3, Ti); E4 = f2mul(E4, Ti);
        };

        auto step = [&](int i, bool do_norm) {
            int li = jo + i;
            float dm = sD[li], xka = sXka[li], xka2 = sXka2[li], xkb = sXkb[li], xkb2 = sXkb2[li];
            Gmk.v = pGmk[li];    Rho.v = pRho[li];     NRho.v = pNRho[li];
            NRho2.v = pNRho2[li]; RhoI.v = pRhoI[li];  NRhoI.v = pNRhoI[li];
            NRhoI2.v = pNRhoI2[li];

            float cp0, cq0, wl0, xl0, yl0, zl0, a00;
            float cp1, cq1, wl1, xl1, yl1, zl1, a01;
            float cp2, cq2, wl2, xl2, yl2, zl2, a02;
            float cp3, cq3, wl3, xl3, yl3, zl3, a03;
            var_lane(wv0, w20, dm, xka, xka2, xkb, xkb2, cp0, cq0, wl0, xl0, yl0, zl0, a00);
            var_lane(wv1, w21, dm, xka, xka2, xkb, xkb2, cp1, cq1, wl1, xl1, yl1, zl1, a01);
            var_lane(wv2_, w22, dm, xka, xka2, xkb, xkb2, cp2, cq2, wl2, xl2, yl2, zl2, a02);
            var_lane(wv3, w23, dm, xka, xka2, xkb, xkb2, cp3, cq3, wl3, xl3, yl3, zl3, a03);

            dnka(W2A, TpA, f2pk(cp0, cp1), f2pk(cq0, cq1), f2pk(wl0, wl1), f2pk(xl0, xl1),
                 f2pk(yl0, yl1), f2pk(zl0, zl1), f2pk(a00, a01), EA0, EA1, EA2, EA3, EA4);
            dnka(W2B, TpB, f2pk(cp2, cp3), f2pk(cq2, cq3), f2pk(wl2, wl3), f2pk(xl2, xl3),
                 f2pk(yl2, yl3), f2pk(zl2, zl3), f2pk(a02, a03), EB0, EB1, EB2, EB3, EB4);

            if (do_norm) {
                normpair(EA0, EA1, EA2, EA3, EA4);
                normpair(EB0, EB1, EB2, EB3, EB4);
            }
        };

        #pragma unroll 1
        for (int i = L_ - 2; i >= 1; i -= 2) {
            step(i, false);
            step(i - 1, true);
        }
        step(0, true);

        float d0, d1, d2, d3;
        f2up(EA0, d0, d1);
        f2up(EB0, d2, d3);
        if (valid) {
            if (is_e00) {
                g_e00[p0 + j] = d0;
            } else {
                float lo = fminf(fminf(d0, d1), fminf(d2, d3));
                float hi = fmaxf(fmaxf(d0, d1), fmaxf(d2, d3));
                atomicMin(&sMnU[j], ford(lo));
                atomicMax(&sMxU[j], ford(hi));
            }
        }
    }
    __syncthreads();
    if (tid < npts) {
        g_rng[p0 + tid] = funord(sMxU[tid]) - funord(sMnU[tid]);
    }
}

// ---------------------------------------------------------------------------
__global__ void __launch_bounds__(128) finalKernel(const float* __restrict__ b,
                                                   float* __restrict__ out) {
    __shared__ float red[4];
    int m = blockIdx.x;
    float acc = 0.0f;
    for (int p = threadIdx.x; p < P_; p += blockDim.x) {
        int idx = m * P_ + p;
        float v = g_e00[idx] / g_rng[idx];
        float pw = __expf(-2.3025850929940457f * fabsf(v));   // 0.1^|v|
        acc += fabsf(pw - 1.0f);
    }
    acc *= (1.0f / (float)P_);
    for (int i = threadIdx.x; i < L_; i += blockDim.x) {
        float bi = b[m * L_ + i];
        float val;
        if (i == 0)            val = bi - b[m * L_ + 1];
        else if (i == L_ - 1)  val = bi - b[m * L_ + L_ - 2];
        else                   val = 2.0f * bi - b[m * L_ + i - 1] - b[m * L_ + i + 1];
        acc += fabsf(val) * (1.0f / (float)L_);
    }
    #pragma unroll
    for (int o = 16; o > 0; o >>= 1) acc += __shfl_xor_sync(0xffffffffu, acc, o);
    int wid = threadIdx.x >> 5;
    if ((threadIdx.x & 31) == 0) red[wid] = acc;
    __syncthreads();
    if (threadIdx.x == 0) out[m] = red[0] + red[1] + red[2] + red[3];
}

// ---------------------------------------------------------------------------
extern "C" void kernel_launch(void* const* d_in, const int* in_sizes, int n_in,
                              void* d_out, int out_size) {
    const float* vlist = (const float*)d_in[0];
    const float* tlist = (const float*)d_in[1];
    const float* d     = (const float*)d_in[2];
    const float* b     = (const float*)d_in[3];
    const float* Clist = (const float*)d_in[4];
    float* out = (float*)d_out;

    dummyKernel<<<1, 32>>>();
    dummyKernel<<<1, 32>>>();
    prepKernel<<<(M_ * L_ + 255) / 256, 256>>>(d, b);
    int nblk = (M_ * P_ + PTS_PER_BLK - 1) / PTS_PER_BLK;
    detKernel<<<nblk, 128>>>(tlist, Clist, vlist);
    dummyKernel<<<1, 32>>>();   // keeps launch positions stable for ncu -s
    finalKernel<<<M_, 128>>>(b, out);
}

// round 7
// speedup vs baseline: 1.1688x; 1.1688x over previous
#include <cuda_runtime.h>

#define M_   64
#define L_   32
#define P_   100
#define NC_  400
#define NPAIR_ (NC_/2)
#define PTS_PER_BLK 3
#define ITEMS_PER_PT (NPAIR_ + 1)          // 200 C-pairs + 1 e00
#define TWO_PI_F 6.28318530717958647692f

typedef unsigned long long ull;

struct Layer { float d, inv_a, inv_b, b2, rho, inv_rho; };

__device__ Layer g_layers[M_ * L_];
__device__ float g_rng[M_ * P_];
__device__ float g_e00[M_ * P_];

// ---------------------------------------------------------------------------
// Packed fp32x2 helpers
// ---------------------------------------------------------------------------
struct F2 { ull v; };
__device__ __forceinline__ F2 f2pk(float a, float b) {
    F2 r; asm("mov.b64 %0,{%1,%2};" : "=l"(r.v) : "f"(a), "f"(b)); return r;
}
__device__ __forceinline__ void f2up(F2 a, float& x, float& y) {
    asm("mov.b64 {%0,%1},%2;" : "=f"(x), "=f"(y) : "l"(a.v));
}
__device__ __forceinline__ F2 f2mul(F2 a, F2 b) {
    F2 r; asm("mul.rn.f32x2 %0,%1,%2;" : "=l"(r.v) : "l"(a.v), "l"(b.v)); return r;
}
__device__ __forceinline__ F2 f2add(F2 a, F2 b) {
    F2 r; asm("add.rn.f32x2 %0,%1,%2;" : "=l"(r.v) : "l"(a.v), "l"(b.v)); return r;
}
__device__ __forceinline__ F2 f2sub(F2 a, F2 b) {
    F2 r; asm("sub.rn.f32x2 %0,%1,%2;" : "=l"(r.v) : "l"(a.v), "l"(b.v)); return r;
}
__device__ __forceinline__ F2 f2fma(F2 a, F2 b, F2 c) {
    F2 r; asm("fma.rn.f32x2 %0,%1,%2,%3;" : "=l"(r.v) : "l"(a.v), "l"(b.v), "l"(c.v)); return r;
}
__device__ __forceinline__ float frsqa(float x) {
    float r; asm("rsqrt.approx.f32 %0,%1;" : "=f"(r) : "f"(x)); return r;
}
__device__ __forceinline__ float fsqrta(float x) {
    float r; asm("sqrt.approx.f32 %0,%1;" : "=f"(r) : "f"(x)); return r;
}
__device__ __forceinline__ ull dupf(float f) {
    unsigned u = __float_as_uint(f); return ((ull)u << 32) | (ull)u;
}
__device__ __forceinline__ unsigned ford(float f) {
    unsigned u = __float_as_uint(f);
    return (u & 0x80000000u) ? ~u : (u | 0x80000000u);
}
__device__ __forceinline__ float funord(unsigned u) {
    return (u & 0x80000000u) ? __uint_as_float(u & 0x7FFFFFFFu) : __uint_as_float(~u);
}

// ---------------------------------------------------------------------------
// _var for one lane (branchless, trimmed). p,q<16 & exa<60 cutoffs are dead
// for this data range. sqrt+rsqrt both from MUFU (no guard sel needed:
// sqrt(0)=0; the w eq-case select covers ira=inf).
// ---------------------------------------------------------------------------
__device__ __forceinline__ void var_lane(
    float wv, float wv2, float dm, float xka, float xka2, float xkb, float xkb2,
    float& cosp, float& cosq, float& w, float& x, float& y, float& z, float& a0)
{
    float ra2 = fabsf(wv2 - xka2), rb2 = fabsf(wv2 - xkb2);
    float ra = fsqrta(ra2), ira = frsqa(ra2);
    float rb = fsqrta(rb2), irb = frsqa(rb2);
    float p = ra * dm, q = rb * dm;
    float sinp, cosp_o; __sincosf(p, &sinp, &cosp_o);
    float sinq, cosq_o; __sincosf(q, &sinq, &cosq_o);
    float ep = __expf(-p), eq_ = __expf(-q);
    float fp = ep * ep, fq = eq_ * eq_;
    float cpe = fmaf(0.5f, fp, 0.5f), spe = fmaf(-0.5f, fp, 0.5f);
    float cqe = fmaf(0.5f, fq, 0.5f), sqe = fmaf(-0.5f, fq, 0.5f);
    bool lt_a = wv < xka, lt_b = wv < xkb;
    bool eq_a = wv == xka, eq_b = wv == xkb;
    float sp = lt_a ? sinp : spe;
    float sq = lt_b ? sinq : sqe;
    cosp = lt_a ? cosp_o : cpe;
    cosq = lt_b ? cosq_o : cqe;
    float wm = sp * ira, ym = sq * irb;
    w = eq_a ? dm : wm;
    y = eq_b ? dm : ym;
    float xm = ra * sp, zm = rb * sq;
    x = lt_a ? -xm : xm;
    z = lt_b ? -zm : zm;
    a0 = (lt_a ? 1.0f : ep) * (lt_b ? 1.0f : eq_);
}

// f-basis halfspace init: f = e_half scaled by sigma(rho_{L-2}) = (1,r,r,r,r^2)
__device__ __forceinline__ void half_lane_f(
    float wv2, float xka2h, float xkb2h, float gmkh,
    float rho2h, float rhh1, float rh4,
    float& f0, float& f1, float& f2v, float& f3, float& f4)
{
    float ra = fsqrta(fabsf(wv2 - xka2h));
    float rb = fsqrta(fabsf(wv2 - xkb2h));
    float gam = gmkh * wv2, gamm1 = gam - 1.0f;
    float rarb = ra * rb;
    f0 = rho2h * (gamm1 * gamm1 - gam * gmkh * rarb);
    f1 = -rhh1 * ra;
    f2v = rhh1 * (gamm1 - gmkh * rarb);
    f3 = rhh1 * rb;
    f4 = rh4 * (wv2 - rarb);
}

// ---------------------------------------------------------------------------
__global__ void prepKernel(const float* __restrict__ d, const float* __restrict__ b) {
    int i = blockIdx.x * blockDim.x + threadIdx.x;
    if (i >= M_ * L_) return;
    float bb = b[i];
    float b2 = bb * bb, b3 = b2 * bb, b4 = b2 * b2;
    float a = 0.9409f + 2.0947f * bb - 0.8206f * b2 + 0.2683f * b3 - 0.0251f * b4;
    float a2 = a * a, a3 = a2 * a, a4 = a2 * a2, a5 = a4 * a;
    float rho = 1.6612f * a - 0.4721f * a2 + 0.0671f * a3 - 0.0043f * a4 + 0.000106f * a5;
    Layer ly;
    ly.d = d[i]; ly.inv_a = 1.0f / a; ly.inv_b = 1.0f / bb;
    ly.b2 = b2;  ly.rho = rho;        ly.inv_rho = 1.0f / rho;
    g_layers[i] = ly;
}

__global__ void dummyKernel() {}   // ncu capture alignment

// ---------------------------------------------------------------------------
// Det grid: 3 points/block, pair items, rho-free dnka (similarity-scaled
// basis) + per-layer diagonal ratio post-scale; norm every 3 layers.
// ---------------------------------------------------------------------------
__global__ void __launch_bounds__(128, 7) detKernel(const float* __restrict__ tlist,
                                                    const float* __restrict__ Clist,
                                                    const float* __restrict__ vlist) {
    __shared__ float sDm[PTS_PER_BLK * L_];
    __shared__ float4 sK2[PTS_PER_BLK * L_];          // xka, xka2, xkb, xkb2
    __shared__ ull pGmk[PTS_PER_BLK * L_], pR[PTS_PER_BLK * L_], pR2[PTS_PER_BLK * L_];
    __shared__ float4 sHSa[PTS_PER_BLK];              // gmk_h, xka2_h, xkb2_h, rho2_h
    __shared__ float2 sHSb[PTS_PER_BLK];              // rhh1 (= rho_h*rho_{L-2}), rh4 (= rho_{L-2}^2)
    __shared__ float sOmg[PTS_PER_BLK], sV[PTS_PER_BLK];
    __shared__ unsigned sMnU[PTS_PER_BLK], sMxU[PTS_PER_BLK];
    __shared__ float shC[NC_];

    int tid = threadIdx.x;
    int p0 = blockIdx.x * PTS_PER_BLK;
    int npts = min(PTS_PER_BLK, M_ * P_ - p0);

    if (tid < npts) {
        int pt = p0 + tid;
        int mi = pt / P_;
        float omega = fmaxf(TWO_PI_F / tlist[pt], 1e-4f);
        float iw = __fdividef(1.0f, omega);
        sOmg[tid] = TWO_PI_F / tlist[pt];
        sV[tid] = vlist[pt];
        sMnU[tid] = 0xFFFFFFFFu;
        sMxU[tid] = 0u;
        Layer hl = g_layers[mi * L_ + L_ - 1];
        Layer l2 = g_layers[mi * L_ + L_ - 2];
        float xka_h = omega * hl.inv_a, xkb_h = omega * hl.inv_b;
        float gmk_h = 2.0f * hl.b2 * iw * iw;
        sHSa[tid] = make_float4(gmk_h, xka_h * xka_h, xkb_h * xkb_h, hl.rho * hl.rho);
        sHSb[tid] = make_float2(hl.rho * l2.rho, l2.rho * l2.rho);
    }
    for (int i = tid; i < npts * L_; i += 128) {
        int s = i >> 5, l = i & 31;
        int pt = p0 + s;
        int mi = pt / P_;
        float omega = fmaxf(TWO_PI_F / tlist[pt], 1e-4f);
        float iw = __fdividef(1.0f, omega);
        Layer ly = g_layers[mi * L_ + l];
        float xka = omega * ly.inv_a, xkb = omega * ly.inv_b;
        float gmk = 2.0f * ly.b2 * iw * iw;
        sDm[i] = ly.d;
        sK2[i] = make_float4(xka, xka * xka, xkb, xkb * xkb);
        pGmk[i] = dupf(gmk);
        float rho_prev = (l == 0) ? 1.0f : g_layers[mi * L_ + l - 1].rho;
        float r = __fdividef(rho_prev, ly.rho);
        pR[i]  = dupf(r);
        pR2[i] = dupf(r * r);
    }
    for (int i = tid; i < NC_; i += 128) shC[i] = Clist[i];
    __syncthreads();

    int nit = npts * ITEMS_PER_PT;
    #pragma unroll 1
    for (int it = tid; it < nit; it += 128) {
        int j = (it >= 2 * ITEMS_PER_PT) ? 2 : ((it >= ITEMS_PER_PT) ? 1 : 0);
        int local = it - j * ITEMS_PER_PT;
        int jo = j << 5;
        bool is_e00 = (local == NPAIR_);
        float omega_raw = sOmg[j];
        float den0 = is_e00 ? sV[j] : shC[2 * local];
        float den1 = is_e00 ? sV[j] : shC[2 * local + 1];
        float wv0 = __fdividef(omega_raw, den0);
        float wv1 = __fdividef(omega_raw, den1);
        float wv20 = wv0 * wv0, wv21 = wv1 * wv1;
        F2 W2 = f2pk(wv20, wv21);
        F2 Tp = f2pk(-2.0f * wv20, -2.0f * wv21);
        F2 ONE = f2pk(1.0f, 1.0f);

        float4 hsa = sHSa[j];
        float2 hsb = sHSb[j];
        F2 E0, E1, E2, E3, E4;
        {
            float a0_, a1_, a2_, a3_, a4_, b0_, b1_, b2_, b3_, b4_;
            half_lane_f(wv20, hsa.y, hsa.z, hsa.x, hsa.w, hsb.x, hsb.y, a0_, a1_, a2_, a3_, a4_);
            half_lane_f(wv21, hsa.y, hsa.z, hsa.x, hsa.w, hsb.x, hsb.y, b0_, b1_, b2_, b3_, b4_);
            E0 = f2pk(a0_, b0_); E1 = f2pk(a1_, b1_); E2 = f2pk(a2_, b2_);
            E3 = f2pk(a3_, b3_); E4 = f2pk(a4_, b4_);
        }

        auto step = [&](int i) {
            int li = jo + i;
            float dm = sDm[li];
            float4 k2 = sK2[li];
            F2 Gmk; Gmk.v = pGmk[li];
            F2 R;   R.v   = pR[li];
            F2 R2;  R2.v  = pR2[li];

            float cp0, cq0, wl0, xl0, yl0, zl0, a00;
            float cp1, cq1, wl1, xl1, yl1, zl1, a01;
            var_lane(wv0, wv20, dm, k2.x, k2.y, k2.z, k2.w, cp0, cq0, wl0, xl0, yl0, zl0, a00);
            var_lane(wv1, wv21, dm, k2.x, k2.y, k2.z, k2.w, cp1, cq1, wl1, xl1, yl1, zl1, a01);
            F2 Cp = f2pk(cp0, cp1), Cq = f2pk(cq0, cq1);
            F2 W = f2pk(wl0, wl1), X = f2pk(xl0, xl1), Y = f2pk(yl0, yl1), Z = f2pk(zl0, zl1);
            F2 A0 = f2pk(a00, a01);

            F2 Gam  = f2mul(Gmk, W2);
            F2 cpcq = f2mul(Cp, Cq);
            F2 cpy = f2mul(Cp, Y), cpz = f2mul(Cp, Z);
            F2 cqw = f2mul(Cq, W), cqx = f2mul(Cq, X);
            F2 xy = f2mul(X, Y), xz = f2mul(X, Z), wy = f2mul(W, Y), wz = f2mul(W, Z);
            F2 gamm1 = f2sub(Gam, ONE);
            F2 twgm1 = f2add(Gam, gamm1);
            F2 gmgmk = f2mul(Gam, Gmk);
            F2 gmgm1 = f2mul(Gam, gamm1);
            F2 gm1sq = f2mul(gamm1, gamm1);
            F2 a0pq  = f2sub(A0, cpcq);
            F2 A2    = f2add(a0pq, a0pq);
            F2 w2wy  = f2mul(W2, wy);

            // rho-free c's (v* carry a leading minus, handled in matvec)
            F2 u = f2fma(gm1sq, w2wy, f2mul(gmgmk, xz));
            u = f2fma(gmgm1, A2, u);
            F2 c00 = f2sub(cpcq, u);
            F2 c01 = f2sub(f2mul(W2, cpy), cqx);
            F2 v02 = f2fma(Gmk, xz, f2mul(gamm1, w2wy));
            v02 = f2fma(twgm1, a0pq, v02);
            F2 c03 = f2sub(cpz, f2mul(W2, cqw));
            F2 v04 = f2fma(W2, A2, xz);
            v04 = f2fma(W2, w2wy, v04);
            F2 c10 = f2sub(f2mul(gmgmk, cpz), f2mul(gm1sq, cqw));
            F2 c12 = f2sub(f2mul(Gmk, cpz), f2mul(gamm1, cqw));
            F2 c30 = f2sub(f2mul(gm1sq, cpy), f2mul(gmgmk, cqx));
            F2 c32 = f2sub(f2mul(gamm1, cpy), f2mul(Gmk, cqx));
            F2 gg   = f2mul(gmgmk, gm1sq);
            F2 gmk2 = f2mul(gmgmk, gmgmk);
            F2 g1q  = f2mul(gm1sq, gm1sq);
            F2 v40 = f2fma(gmk2, xz, f2mul(g1q, wy));
            v40 = f2fma(gg, A2, v40);
            F2 k1 = f2mul(f2mul(Gmk, gamm1), twgm1);
            F2 kk2 = f2mul(gmgmk, Gmk);
            F2 kk3 = f2mul(gamm1, gm1sq);
            F2 v42 = f2fma(kk2, xz, f2mul(kk3, wy));
            v42 = f2fma(k1, a0pq, v42);
            F2 dd = f2sub(cpcq, c00);
            F2 c22 = f2add(A0, f2add(dd, dd));
            F2 E2t = f2mul(Tp, E2);

            // matvec with e2t factoring and explicit sign chains
            F2 pos0 = f2fma(E0, c00, f2fma(E1, c10, f2mul(E3, c30)));
            F2 neg0 = f2fma(E2t, v42, f2mul(E4, v40));
            F2 ee0 = f2sub(pos0, neg0);
            F2 ee1 = f2fma(E0, c01, f2fma(E1, cpcq, f2fma(E2t, c32,
                        f2sub(f2mul(E4, c30), f2mul(E3, xy)))));
            F2 pos2 = f2fma(E1, c12, f2fma(E2, c22, f2mul(E3, c32)));
            F2 neg2 = f2fma(E0, v02, f2mul(E4, v42));
            F2 ee2 = f2sub(pos2, neg2);
            F2 ee3 = f2fma(E0, c03, f2fma(E2t, c12, f2fma(E3, cpcq,
                        f2sub(f2mul(E4, c10), f2mul(E1, wz)))));
            F2 pos4 = f2fma(E1, c03, f2fma(E3, c01, f2mul(E4, c00)));
            F2 neg4 = f2fma(E0, v04, f2mul(E2t, v02));
            F2 ee4 = f2sub(pos4, neg4);

            // diagonal ratio post-scale: component 0 unscaled
            E0 = ee0;
            E1 = f2mul(ee1, R);
            E2 = f2mul(ee2, R);
            E3 = f2mul(ee3, R);
            E4 = f2mul(ee4, R2);
        };

        auto norm = [&]() {
            float g0, q0, g1, q1, g2, q2, g3, q3, g4, q4;
            f2up(E0, g0, q0); f2up(E1, g1, q1); f2up(E2, g2, q2);
            f2up(E3, g3, q3); f2up(E4, g4, q4);
            float t1a = fmaxf(fmaxf(fabsf(g0), fabsf(g1)),
                              fmaxf(fmaxf(fabsf(g2), fabsf(g3)), fabsf(g4)));
            float t1b = fmaxf(fmaxf(fabsf(q0), fabsf(q1)),
                              fmaxf(fmaxf(fabsf(q2), fabsf(q3)), fabsf(q4)));
            t1a = fmaxf(t1a, 1e-30f);
            t1b = fmaxf(t1b, 1e-30f);
            F2 Ti = f2pk(__fdividef(1.0f, t1a), __fdividef(1.0f, t1b));
            E0 = f2mul(E0, Ti); E1 = f2mul(E1, Ti); E2 = f2mul(E2, Ti);
            E3 = f2mul(E3, Ti); E4 = f2mul(E4, Ti);
        };

        // layers 30..1 in triples (norm each triple), then layer 0 + final norm
        #pragma unroll 1
        for (int i = L_ - 2; i >= 3; i -= 3) {
            step(i); step(i - 1); step(i - 2);
            norm();
        }
        step(0);
        norm();

        float d0, d1;
        f2up(E0, d0, d1);
        if (is_e00) {
            g_e00[p0 + j] = d0;
        } else {
            float lo = fminf(d0, d1), hi = fmaxf(d0, d1);
            atomicMin(&sMnU[j], ford(lo));
            atomicMax(&sMxU[j], ford(hi));
        }
    }
    __syncthreads();
    if (tid < npts) {
        g_rng[p0 + tid] = funord(sMxU[tid]) - funord(sMnU[tid]);
    }
}

// ---------------------------------------------------------------------------
__global__ void __launch_bounds__(128) finalKernel(const float* __restrict__ b,
                                                   float* __restrict__ out) {
    __shared__ float red[4];
    int m = blockIdx.x;
    float acc = 0.0f;
    for (int p = threadIdx.x; p < P_; p += blockDim.x) {
        int idx = m * P_ + p;
        float v = g_e00[idx] / g_rng[idx];
        float pw = __expf(-2.3025850929940457f * fabsf(v));   // 0.1^|v|
        acc += fabsf(pw - 1.0f);
    }
    acc *= (1.0f / (float)P_);
    for (int i = threadIdx.x; i < L_; i += blockDim.x) {
        float bi = b[m * L_ + i];
        float val;
        if (i == 0)            val = bi - b[m * L_ + 1];
        else if (i == L_ - 1)  val = bi - b[m * L_ + L_ - 2];
        else                   val = 2.0f * bi - b[m * L_ + i - 1] - b[m * L_ + i + 1];
        acc += fabsf(val) * (1.0f / (float)L_);
    }
    #pragma unroll
    for (int o = 16; o > 0; o >>= 1) acc += __shfl_xor_sync(0xffffffffu, acc, o);
    int wid = threadIdx.x >> 5;
    if ((threadIdx.x & 31) == 0) red[wid] = acc;
    __syncthreads();
    if (threadIdx.x == 0) out[m] = red[0] + red[1] + red[2] + red[3];
}

// ---------------------------------------------------------------------------
extern "C" void kernel_launch(void* const* d_in, const int* in_sizes, int n_in,
                              void* d_out, int out_size) {
    const float* vlist = (const float*)d_in[0];
    const float* tlist = (const float*)d_in[1];
    const float* d     = (const float*)d_in[2];
    const float* b     = (const float*)d_in[3];
    const float* Clist = (const float*)d_in[4];
    float* out = (float*)d_out;

    dummyKernel<<<1, 32>>>();
    dummyKernel<<<1, 32>>>();
    prepKernel<<<(M_ * L_ + 255) / 256, 256>>>(d, b);
    int nblk = (M_ * P_ + PTS_PER_BLK - 1) / PTS_PER_BLK;
    detKernel<<<nblk, 128>>>(tlist, Clist, vlist);
    dummyKernel<<<1, 32>>>();   // keeps launch positions stable for ncu -s
    finalKernel<<<M_, 128>>>(b, out);
}

// round 9
// speedup vs baseline: 1.1744x; 1.0047x over previous
#include <cuda_runtime.h>

#define M_   64
#define L_   32
#define P_   100
#define NC_  400
#define NPAIR_ (NC_/2)
#define PTS_PER_BLK 3
#define ITEMS_PER_PT (NPAIR_ + 1)          // 200 C-pairs + 1 e00
#define TWO_PI_F 6.28318530717958647692f

typedef unsigned long long ull;

struct Layer { float d, inv_a, inv_b, b2, rho, inv_rho; };

__device__ Layer g_layers[M_ * L_];
__device__ float g_rng[M_ * P_];
__device__ float g_e00[M_ * P_];

// ---------------------------------------------------------------------------
// Packed fp32x2 helpers
// ---------------------------------------------------------------------------
struct F2 { ull v; };
__device__ __forceinline__ F2 f2pk(float a, float b) {
    F2 r; asm("mov.b64 %0,{%1,%2};" : "=l"(r.v) : "f"(a), "f"(b)); return r;
}
__device__ __forceinline__ void f2up(F2 a, float& x, float& y) {
    asm("mov.b64 {%0,%1},%2;" : "=f"(x), "=f"(y) : "l"(a.v));
}
__device__ __forceinline__ F2 f2mul(F2 a, F2 b) {
    F2 r; asm("mul.rn.f32x2 %0,%1,%2;" : "=l"(r.v) : "l"(a.v), "l"(b.v)); return r;
}
__device__ __forceinline__ F2 f2add(F2 a, F2 b) {
    F2 r; asm("add.rn.f32x2 %0,%1,%2;" : "=l"(r.v) : "l"(a.v), "l"(b.v)); return r;
}
__device__ __forceinline__ F2 f2sub(F2 a, F2 b) {
    F2 r; asm("sub.rn.f32x2 %0,%1,%2;" : "=l"(r.v) : "l"(a.v), "l"(b.v)); return r;
}
__device__ __forceinline__ F2 f2fma(F2 a, F2 b, F2 c) {
    F2 r; asm("fma.rn.f32x2 %0,%1,%2,%3;" : "=l"(r.v) : "l"(a.v), "l"(b.v), "l"(c.v)); return r;
}
__device__ __forceinline__ float frsqa(float x) {
    float r; asm("rsqrt.approx.f32 %0,%1;" : "=f"(r) : "f"(x)); return r;
}
__device__ __forceinline__ float fsqrta(float x) {
    float r; asm("sqrt.approx.f32 %0,%1;" : "=f"(r) : "f"(x)); return r;
}
__device__ __forceinline__ ull dupf(float f) {
    unsigned u = __float_as_uint(f); return ((ull)u << 32) | (ull)u;
}
__device__ __forceinline__ unsigned ford(float f) {
    unsigned u = __float_as_uint(f);
    return (u & 0x80000000u) ? ~u : (u | 0x80000000u);
}
__device__ __forceinline__ float funord(unsigned u) {
    return (u & 0x80000000u) ? __uint_as_float(u & 0x7FFFFFFFu) : __uint_as_float(~u);
}

// f-basis halfspace init (scaled by sigma(rho_{L-2}) = (1,r,r,r,r^2))
__device__ __forceinline__ void half_lane_f(
    float wv2, float xka2h, float xkb2h, float gmkh,
    float rho2h, float rhh1, float rh4,
    float& f0, float& f1, float& f2v, float& f3, float& f4)
{
    float ra = fsqrta(fabsf(wv2 - xka2h));
    float rb = fsqrta(fabsf(wv2 - xkb2h));
    float gam = gmkh * wv2, gamm1 = gam - 1.0f;
    float rarb = ra * rb;
    f0 = rho2h * (gamm1 * gamm1 - gam * gmkh * rarb);
    f1 = -rhh1 * ra;
    f2v = rhh1 * (gamm1 - gmkh * rarb);
    f3 = rhh1 * rb;
    f4 = rh4 * (wv2 - rarb);
}

// ---------------------------------------------------------------------------
__global__ void prepKernel(const float* __restrict__ d, const float* __restrict__ b) {
    int i = blockIdx.x * blockDim.x + threadIdx.x;
    if (i >= M_ * L_) return;
    float bb = b[i];
    float b2 = bb * bb, b3 = b2 * bb, b4 = b2 * b2;
    float a = 0.9409f + 2.0947f * bb - 0.8206f * b2 + 0.2683f * b3 - 0.0251f * b4;
    float a2 = a * a, a3 = a2 * a, a4 = a2 * a2, a5 = a4 * a;
    float rho = 1.6612f * a - 0.4721f * a2 + 0.0671f * a3 - 0.0043f * a4 + 0.000106f * a5;
    Layer ly;
    ly.d = d[i]; ly.inv_a = 1.0f / a; ly.inv_b = 1.0f / bb;
    ly.b2 = b2;  ly.rho = rho;        ly.inv_rho = 1.0f / rho;
    g_layers[i] = ly;
}

__global__ void dummyKernel() {}   // ncu capture alignment

// ---------------------------------------------------------------------------
// Det grid: rho-free dnka with NCq factoring, c22=A0+2u identity, packed var
// tail. Norm every 3 layers.
// ---------------------------------------------------------------------------
__global__ void __launch_bounds__(128, 6) detKernel(const float* __restrict__ tlist,
                                                    const float* __restrict__ Clist,
                                                    const float* __restrict__ vlist) {
    __shared__ float sDm[PTS_PER_BLK * L_];
    __shared__ float2 sKab[PTS_PER_BLK * L_];         // xka, xkb (scalar compares)
    __shared__ ull pDm[PTS_PER_BLK * L_], pXka2[PTS_PER_BLK * L_], pXkb2[PTS_PER_BLK * L_];
    __shared__ ull pGmk[PTS_PER_BLK * L_], pR[PTS_PER_BLK * L_], pR2[PTS_PER_BLK * L_];
    __shared__ float4 sHSa[PTS_PER_BLK];              // gmk_h, xka2_h, xkb2_h, rho2_h
    __shared__ float2 sHSb[PTS_PER_BLK];              // rho_h*rho_{L-2}, rho_{L-2}^2
    __shared__ float sOmg[PTS_PER_BLK], sV[PTS_PER_BLK];
    __shared__ unsigned sMnU[PTS_PER_BLK], sMxU[PTS_PER_BLK];
    __shared__ float shC[NC_];

    int tid = threadIdx.x;
    int p0 = blockIdx.x * PTS_PER_BLK;
    int npts = min(PTS_PER_BLK, M_ * P_ - p0);

    if (tid < npts) {
        int pt = p0 + tid;
        int mi = pt / P_;
        float omega = fmaxf(TWO_PI_F / tlist[pt], 1e-4f);
        float iw = __fdividef(1.0f, omega);
        sOmg[tid] = TWO_PI_F / tlist[pt];
        sV[tid] = vlist[pt];
        sMnU[tid] = 0xFFFFFFFFu;
        sMxU[tid] = 0u;
        Layer hl = g_layers[mi * L_ + L_ - 1];
        Layer l2 = g_layers[mi * L_ + L_ - 2];
        float xka_h = omega * hl.inv_a, xkb_h = omega * hl.inv_b;
        float gmk_h = 2.0f * hl.b2 * iw * iw;
        sHSa[tid] = make_float4(gmk_h, xka_h * xka_h, xkb_h * xkb_h, hl.rho * hl.rho);
        sHSb[tid] = make_float2(hl.rho * l2.rho, l2.rho * l2.rho);
    }
    for (int i = tid; i < npts * L_; i += 128) {
        int s = i >> 5, l = i & 31;
        int pt = p0 + s;
        int mi = pt / P_;
        float omega = fmaxf(TWO_PI_F / tlist[pt], 1e-4f);
        float iw = __fdividef(1.0f, omega);
        Layer ly = g_layers[mi * L_ + l];
        float xka = omega * ly.inv_a, xkb = omega * ly.inv_b;
        float gmk = 2.0f * ly.b2 * iw * iw;
        sDm[i] = ly.d;
        sKab[i] = make_float2(xka, xkb);
        pDm[i]   = dupf(ly.d);
        pXka2[i] = dupf(xka * xka);
        pXkb2[i] = dupf(xkb * xkb);
        pGmk[i]  = dupf(gmk);
        float rho_prev = (l == 0) ? 1.0f : g_layers[mi * L_ + l - 1].rho;
        float r = __fdividef(rho_prev, ly.rho);
        pR[i]  = dupf(r);
        pR2[i] = dupf(r * r);
    }
    for (int i = tid; i < NC_; i += 128) shC[i] = Clist[i];
    __syncthreads();

    const F2 ONE   = f2pk(1.0f, 1.0f);
    const F2 HALF  = f2pk(0.5f, 0.5f);
    const F2 NHALF = f2pk(-0.5f, -0.5f);
    const F2 TWO   = f2pk(2.0f, 2.0f);
    const F2 NONEG = f2pk(-1.0f, -1.0f);

    int nit = npts * ITEMS_PER_PT;
    #pragma unroll 1
    for (int it = tid; it < nit; it += 128) {
        int j = (it >= 2 * ITEMS_PER_PT) ? 2 : ((it >= ITEMS_PER_PT) ? 1 : 0);
        int local = it - j * ITEMS_PER_PT;
        int jo = j << 5;
        bool is_e00 = (local == NPAIR_);
        float omega_raw = sOmg[j];
        float den0 = is_e00 ? sV[j] : shC[2 * local];
        float den1 = is_e00 ? sV[j] : shC[2 * local + 1];
        float wv0 = __fdividef(omega_raw, den0);
        float wv1 = __fdividef(omega_raw, den1);
        float w20 = wv0 * wv0, w21 = wv1 * wv1;
        F2 W2 = f2pk(w20, w21);
        F2 Tp = f2pk(-2.0f * w20, -2.0f * w21);

        float4 hsa = sHSa[j];
        float2 hsb = sHSb[j];
        F2 E0, E1, E2, E3, E4;
        {
            float a0_, a1_, a2_, a3_, a4_, b0_, b1_, b2_, b3_, b4_;
            half_lane_f(w20, hsa.y, hsa.z, hsa.x, hsa.w, hsb.x, hsb.y, a0_, a1_, a2_, a3_, a4_);
            half_lane_f(w21, hsa.y, hsa.z, hsa.x, hsa.w, hsb.x, hsb.y, b0_, b1_, b2_, b3_, b4_);
            E0 = f2pk(a0_, b0_); E1 = f2pk(a1_, b1_); E2 = f2pk(a2_, b2_);
            E3 = f2pk(a3_, b3_); E4 = f2pk(a4_, b4_);
        }

        auto step = [&](int i) {
            int li = jo + i;
            float dm = sDm[li];
            float2 kab = sKab[li];
            F2 DM;    DM.v    = pDm[li];
            F2 XKA2;  XKA2.v  = pXka2[li];
            F2 XKB2;  XKB2.v  = pXkb2[li];
            F2 Gmk;   Gmk.v   = pGmk[li];
            F2 R;     R.v     = pR[li];
            F2 R2;    R2.v    = pR2[li];

            // ---- var (packed tail) ----
            float ra2_0, ra2_1, rb2_0, rb2_1;
            F2 RA2 = f2sub(W2, XKA2); f2up(RA2, ra2_0, ra2_1);
            F2 RB2 = f2sub(W2, XKB2); f2up(RB2, rb2_0, rb2_1);
            float ra0 = fsqrta(fabsf(ra2_0)), ira0 = frsqa(fabsf(ra2_0));
            float ra1 = fsqrta(fabsf(ra2_1)), ira1 = frsqa(fabsf(ra2_1));
            float rb0 = fsqrta(fabsf(rb2_0)), irb0 = frsqa(fabsf(rb2_0));
            float rb1 = fsqrta(fabsf(rb2_1)), irb1 = frsqa(fabsf(rb2_1));
            F2 RA = f2pk(ra0, ra1), RB = f2pk(rb0, rb1);
            F2 IRA = f2pk(ira0, ira1), IRB = f2pk(irb0, irb1);
            F2 P = f2mul(RA, DM), Q = f2mul(RB, DM);
            float pp0, pp1, qq0, qq1;
            f2up(P, pp0, pp1); f2up(Q, qq0, qq1);
            float snp0, csp0, snp1, csp1, snq0, csq0, snq1, csq1;
            __sincosf(pp0, &snp0, &csp0);
            __sincosf(pp1, &snp1, &csp1);
            __sincosf(qq0, &snq0, &csq0);
            __sincosf(qq1, &snq1, &csq1);
            float ep0 = __expf(-pp0), ep1 = __expf(-pp1);
            float eqv0 = __expf(-qq0), eqv1 = __expf(-qq1);
            F2 EP = f2pk(ep0, ep1), EQ = f2pk(eqv0, eqv1);
            F2 FP = f2mul(EP, EP), FQ = f2mul(EQ, EQ);
            F2 CPE = f2fma(HALF, FP, HALF), SPE = f2fma(NHALF, FP, HALF);
            F2 CQE = f2fma(HALF, FQ, HALF), SQE = f2fma(NHALF, FQ, HALF);
            float cpe0, cpe1, spe0, spe1, cqe0, cqe1, sqe0, sqe1;
            f2up(CPE, cpe0, cpe1); f2up(SPE, spe0, spe1);
            f2up(CQE, cqe0, cqe1); f2up(SQE, sqe0, sqe1);

            bool lta0 = wv0 < kab.x, ltb0 = wv0 < kab.y;
            bool lta1 = wv1 < kab.x, ltb1 = wv1 < kab.y;
            bool eqa0 = wv0 == kab.x, eqb0 = wv0 == kab.y;
            bool eqa1 = wv1 == kab.x, eqb1 = wv1 == kab.y;

            float cp0 = lta0 ? csp0 : cpe0, cp1 = lta1 ? csp1 : cpe1;
            float cq0 = ltb0 ? csq0 : cqe0, cq1 = ltb1 ? csq1 : cqe1;
            float sp0 = lta0 ? snp0 : spe0, sp1 = lta1 ? snp1 : spe1;
            float sq0 = ltb0 ? snq0 : sqe0, sq1 = ltb1 ? snq1 : sqe1;
            float sx0 = lta0 ? -snp0 : spe0, sx1 = lta1 ? -snp1 : spe1;
            float sz0 = ltb0 ? -snq0 : sqe0, sz1 = ltb1 ? -snq1 : sqe1;
            float ea0 = lta0 ? 1.0f : ep0, ea1 = lta1 ? 1.0f : ep1;
            float eb0 = ltb0 ? 1.0f : eqv0, eb1 = ltb1 ? 1.0f : eqv1;

            F2 Cp = f2pk(cp0, cp1), Cq = f2pk(cq0, cq1);
            F2 SP = f2pk(sp0, sp1), SQ = f2pk(sq0, sq1);
            F2 SX = f2pk(sx0, sx1), SZ = f2pk(sz0, sz1);
            F2 A0 = f2mul(f2pk(ea0, ea1), f2pk(eb0, eb1));
            F2 Wm = f2mul(SP, IRA), Ym = f2mul(SQ, IRB);
            F2 X = f2mul(RA, SX), Z = f2mul(RB, SZ);
            float wm0, wm1, ym0, ym1;
            f2up(Wm, wm0, wm1); f2up(Ym, ym0, ym1);
            wm0 = eqa0 ? dm : wm0; wm1 = eqa1 ? dm : wm1;
            ym0 = eqb0 ? dm : ym0; ym1 = eqb1 ? dm : ym1;
            F2 W = f2pk(wm0, wm1), Y = f2pk(ym0, ym1);

            // ---- dnka (rho-free, NCq factoring) ----
            F2 Gam  = f2mul(Gmk, W2);
            F2 cpcq = f2mul(Cp, Cq);
            F2 cpy = f2mul(Cp, Y), cpz = f2mul(Cp, Z);
            F2 NCq = f2mul(Cq, NONEG);
            F2 NCQX = f2mul(NCq, X), NCQW = f2mul(NCq, W);
            F2 xy = f2mul(X, Y), xz = f2mul(X, Z), wy = f2mul(W, Y), wz = f2mul(W, Z);
            F2 gamm1 = f2sub(Gam, ONE);
            F2 twgm1 = f2add(Gam, gamm1);
            F2 gmgmk = f2mul(Gam, Gmk);
            F2 gmgm1 = f2mul(Gam, gamm1);
            F2 gm1sq = f2mul(gamm1, gamm1);
            F2 a0pq  = f2sub(A0, cpcq);
            F2 A2    = f2add(a0pq, a0pq);
            F2 w2wy  = f2mul(W2, wy);

            F2 u = f2fma(gm1sq, w2wy, f2mul(gmgmk, xz));
            u = f2fma(gmgm1, A2, u);
            F2 c00 = f2sub(cpcq, u);
            F2 c01 = f2fma(W2, cpy, NCQX);
            F2 v02 = f2fma(Gmk, xz, f2mul(gamm1, w2wy));
            v02 = f2fma(twgm1, a0pq, v02);
            F2 c03 = f2fma(W2, NCQW, cpz);
            F2 v04 = f2fma(W2, A2, xz);
            v04 = f2fma(W2, w2wy, v04);
            F2 c10 = f2fma(gmgmk, cpz, f2mul(gm1sq, NCQW));
            F2 c12 = f2fma(Gmk, cpz, f2mul(gamm1, NCQW));
            F2 c30 = f2fma(gm1sq, cpy, f2mul(gmgmk, NCQX));
            F2 c32 = f2fma(gamm1, cpy, f2mul(Gmk, NCQX));
            F2 gg   = f2mul(gmgmk, gm1sq);
            F2 gmk2 = f2mul(gmgmk, gmgmk);
            F2 g1q  = f2mul(gm1sq, gm1sq);
            F2 v40 = f2fma(gmk2, xz, f2mul(g1q, wy));
            v40 = f2fma(gg, A2, v40);
            F2 k1 = f2mul(f2mul(Gmk, gamm1), twgm1);
            F2 kk2 = f2mul(gmgmk, Gmk);
            F2 kk3 = f2mul(gamm1, gm1sq);
            F2 v42 = f2fma(kk2, xz, f2mul(kk3, wy));
            v42 = f2fma(k1, a0pq, v42);
            F2 c22 = f2fma(TWO, u, A0);
            F2 E2t = f2mul(Tp, E2);

            // ---- matvec ----
            F2 pos0 = f2fma(E0, c00, f2fma(E1, c10, f2mul(E3, c30)));
            F2 neg0 = f2fma(E2t, v42, f2mul(E4, v40));
            F2 ee0 = f2sub(pos0, neg0);
            F2 ee1 = f2fma(E0, c01, f2fma(E1, cpcq, f2fma(E2t, c32,
                        f2sub(f2mul(E4, c30), f2mul(E3, xy)))));
            F2 pos2 = f2fma(E1, c12, f2fma(E2, c22, f2mul(E3, c32)));
            F2 neg2 = f2fma(E0, v02, f2mul(E4, v42));
            F2 ee2 = f2sub(pos2, neg2);
            F2 ee3 = f2fma(E0, c03, f2fma(E2t, c12, f2fma(E3, cpcq,
                        f2sub(f2mul(E4, c10), f2mul(E1, wz)))));
            F2 pos4 = f2fma(E1, c03, f2fma(E3, c01, f2mul(E4, c00)));
            F2 neg4 = f2fma(E0, v04, f2mul(E2t, v02));
            F2 ee4 = f2sub(pos4, neg4);

            E0 = ee0;
            E1 = f2mul(ee1, R);
            E2 = f2mul(ee2, R);
            E3 = f2mul(ee3, R);
            E4 = f2mul(ee4, R2);
        };

        auto norm = [&]() {
            float g0, q0, g1, q1, g2, q2, g3, q3, g4, q4;
            f2up(E0, g0, q0); f2up(E1, g1, q1); f2up(E2, g2, q2);
            f2up(E3, g3, q3); f2up(E4, g4, q4);
            float t1a = fmaxf(fmaxf(fabsf(g0), fabsf(g1)),
                              fmaxf(fmaxf(fabsf(g2), fabsf(g3)), fabsf(g4)));
            float t1b = fmaxf(fmaxf(fabsf(q0), fabsf(q1)),
                              fmaxf(fmaxf(fabsf(q2), fabsf(q3)), fabsf(q4)));
            t1a = fmaxf(t1a, 1e-30f);
            t1b = fmaxf(t1b, 1e-30f);
            F2 Ti = f2pk(__fdividef(1.0f, t1a), __fdividef(1.0f, t1b));
            E0 = f2mul(E0, Ti); E1 = f2mul(E1, Ti); E2 = f2mul(E2, Ti);
            E3 = f2mul(E3, Ti); E4 = f2mul(E4, Ti);
        };

        #pragma unroll 1
        for (int i = L_ - 2; i >= 3; i -= 3) {
            step(i); step(i - 1); step(i - 2);
            norm();
        }
        step(0);
        norm();

        float d0, d1;
        f2up(E0, d0, d1);
        if (is_e00) {
            g_e00[p0 + j] = d0;
        } else {
            float lo = fminf(d0, d1), hi = fmaxf(d0, d1);
            atomicMin(&sMnU[j], ford(lo));
            atomicMax(&sMxU[j], ford(hi));
        }
    }
    __syncthreads();
    if (tid < npts) {
        g_rng[p0 + tid] = funord(sMxU[tid]) - funord(sMnU[tid]);
    }
}

// ---------------------------------------------------------------------------
__global__ void __launch_bounds__(128) finalKernel(const float* __restrict__ b,
                                                   float* __restrict__ out) {
    __shared__ float red[4];
    int m = blockIdx.x;
    float acc = 0.0f;
    for (int p = threadIdx.x; p < P_; p += blockDim.x) {
        int idx = m * P_ + p;
        float v = g_e00[idx] / g_rng[idx];
        float pw = __expf(-2.3025850929940457f * fabsf(v));   // 0.1^|v|
        acc += fabsf(pw - 1.0f);
    }
    acc *= (1.0f / (float)P_);
    for (int i = threadIdx.x; i < L_; i += blockDim.x) {
        float bi = b[m * L_ + i];
        float val;
        if (i == 0)            val = bi - b[m * L_ + 1];
        else if (i == L_ - 1)  val = bi - b[m * L_ + L_ - 2];
        else                   val = 2.0f * bi - b[m * L_ + i - 1] - b[m * L_ + i + 1];
        acc += fabsf(val) * (1.0f / (float)L_);
    }
    #pragma unroll
    for (int o = 16; o > 0; o >>= 1) acc += __shfl_xor_sync(0xffffffffu, acc, o);
    int wid = threadIdx.x >> 5;
    if ((threadIdx.x & 31) == 0) red[wid] = acc;
    __syncthreads();
    if (threadIdx.x == 0) out[m] = red[0] + red[1] + red[2] + red[3];
}

// ---------------------------------------------------------------------------
extern "C" void kernel_launch(void* const* d_in, const int* in_sizes, int n_in,
                              void* d_out, int out_size) {
    const float* vlist = (const float*)d_in[0];
    const float* tlist = (const float*)d_in[1];
    const float* d     = (const float*)d_in[2];
    const float* b     = (const float*)d_in[3];
    const float* Clist = (const float*)d_in[4];
    float* out = (float*)d_out;

    dummyKernel<<<1, 32>>>();
    dummyKernel<<<1, 32>>>();
    prepKernel<<<(M_ * L_ + 255) / 256, 256>>>(d, b);
    int nblk = (M_ * P_ + PTS_PER_BLK - 1) / PTS_PER_BLK;
    detKernel<<<nblk, 128>>>(tlist, Clist, vlist);
    dummyKernel<<<1, 32>>>();   // keeps launch positions stable for ncu -s
    finalKernel<<<M_, 128>>>(b, out);
}